// round 1
// baseline (speedup 1.0000x reference)
#include <cuda_runtime.h>

// Problem constants (fixed by the dataset)
#define BB 4096
#define CC 32
#define DD 128
#define RR 8

#define WARPS 8
#define ROWS_PER_WARP 8
#define ROWS_PER_CTA (WARPS * ROWS_PER_WARP)   // 64
#define THREADS (WARPS * 32)                   // 256

// Shared memory layout (floats):
//   Ws : 128 rows x 132 (padded)  = 16896
//   Ss : 64 rows  x 128           = 8192
//   As : 32 x 128                 = 4096
//   Cs : 32 x 128                 = 4096
//   Ds : 32 x 128                 = 4096
#define WS_STRIDE 132
#define SMEM_FLOATS (128 * WS_STRIDE + ROWS_PER_CTA * DD + 3 * CC * DD)
#define SMEM_BYTES (SMEM_FLOATS * 4)

__device__ __forceinline__ float tanh_approx(float x) {
    float y;
    asm("tanh.approx.f32 %0, %1;" : "=f"(y) : "f"(x));
    return y;
}

__global__ __launch_bounds__(THREADS, 1)
void rotation_kernel(const float* __restrict__ src,
                     const float* __restrict__ dat,
                     const float* __restrict__ Wg,
                     const float* __restrict__ Ag,
                     const float* __restrict__ Cg,
                     const float* __restrict__ Dg,
                     float* __restrict__ out)
{
    extern __shared__ float sm[];
    float* Ws = sm;                          // [128][132]
    float* Ss = Ws + 128 * WS_STRIDE;        // [64][128]
    float* As = Ss + ROWS_PER_CTA * DD;      // [32][128]
    float* Cs = As + CC * DD;
    float* Ds = Cs + CC * DD;

    const int tid  = threadIdx.x;
    const int lane = tid & 31;
    const int wrp  = tid >> 5;
    const long g0  = (long)blockIdx.x * ROWS_PER_CTA;   // first global row
    const int rowbase = wrp * ROWS_PER_WARP;            // first row (within CTA) for this warp

    // ---- stage source tile (once per CTA), float4 coalesced ----
    {
        const float4* sg = (const float4*)(src + g0 * DD);
        float4* ss = (float4*)Ss;
        #pragma unroll
        for (int t = 0; t < (ROWS_PER_CTA * DD / 4) / THREADS; t++)   // 8 iters
            ss[tid + t * THREADS] = sg[tid + t * THREADS];
    }

    // ---- x (data) lives in registers across all reflections ----
    float x[ROWS_PER_WARP][4];
    #pragma unroll
    for (int j = 0; j < ROWS_PER_WARP; j++) {
        const float* dr = dat + (g0 + rowbase + j) * DD;
        #pragma unroll
        for (int k = 0; k < 4; k++)
            x[j][k] = dr[lane + 32 * k];
    }

    for (int r = 0; r < RR; r++) {
        __syncthreads();   // previous iteration done with Ws/As/Cs/Ds

        // ---- stage W[r] with padded stride (conflict-free compute reads) ----
        {
            const float4* wg = (const float4*)(Wg + (long)r * DD * DD);
            #pragma unroll
            for (int t = 0; t < 16; t++) {
                int idx = tid + t * THREADS;         // 0..4095
                int o   = idx >> 5;                  // output row
                int i4  = idx & 31;                  // float4 index along i
                float4 v4 = wg[idx];
                *(float4*)(Ws + o * WS_STRIDE + i4 * 4) = v4;
            }
        }
        // ---- stage a/c/d[r] ----
        {
            const float4* ag = (const float4*)(Ag + (long)r * CC * DD);
            const float4* cg = (const float4*)(Cg + (long)r * CC * DD);
            const float4* dg = (const float4*)(Dg + (long)r * CC * DD);
            #pragma unroll
            for (int t = 0; t < (CC * DD / 4) / THREADS; t++) {   // 4 iters
                int idx = tid + t * THREADS;
                ((float4*)As)[idx] = ag[idx];
                ((float4*)Cs)[idx] = cg[idx];
                ((float4*)Ds)[idx] = dg[idx];
            }
        }
        __syncthreads();

        // ---- GEMM: acc[j][k] = sum_i W[r][o][i] * s[row_j][i],  o = lane + 32k ----
        float acc[ROWS_PER_WARP][4];
        #pragma unroll
        for (int j = 0; j < ROWS_PER_WARP; j++)
            #pragma unroll
            for (int k = 0; k < 4; k++) acc[j][k] = 0.f;

        const float* w0p = Ws + (lane +  0) * WS_STRIDE;
        const float* w1p = Ws + (lane + 32) * WS_STRIDE;
        const float* w2p = Ws + (lane + 64) * WS_STRIDE;
        const float* w3p = Ws + (lane + 96) * WS_STRIDE;
        const float* sp  = Ss + rowbase * DD;

        #pragma unroll 2
        for (int i4 = 0; i4 < 32; i4++) {
            float4 w0 = *(const float4*)(w0p + i4 * 4);
            float4 w1 = *(const float4*)(w1p + i4 * 4);
            float4 w2 = *(const float4*)(w2p + i4 * 4);
            float4 w3 = *(const float4*)(w3p + i4 * 4);
            #pragma unroll
            for (int j = 0; j < ROWS_PER_WARP; j++) {
                float4 s = *(const float4*)(sp + j * DD + i4 * 4);
                acc[j][0] = fmaf(w0.x, s.x, acc[j][0]);
                acc[j][0] = fmaf(w0.y, s.y, acc[j][0]);
                acc[j][0] = fmaf(w0.z, s.z, acc[j][0]);
                acc[j][0] = fmaf(w0.w, s.w, acc[j][0]);
                acc[j][1] = fmaf(w1.x, s.x, acc[j][1]);
                acc[j][1] = fmaf(w1.y, s.y, acc[j][1]);
                acc[j][1] = fmaf(w1.z, s.z, acc[j][1]);
                acc[j][1] = fmaf(w1.w, s.w, acc[j][1]);
                acc[j][2] = fmaf(w2.x, s.x, acc[j][2]);
                acc[j][2] = fmaf(w2.y, s.y, acc[j][2]);
                acc[j][2] = fmaf(w2.z, s.z, acc[j][2]);
                acc[j][2] = fmaf(w2.w, s.w, acc[j][2]);
                acc[j][3] = fmaf(w3.x, s.x, acc[j][3]);
                acc[j][3] = fmaf(w3.y, s.y, acc[j][3]);
                acc[j][3] = fmaf(w3.z, s.z, acc[j][3]);
                acc[j][3] = fmaf(w3.w, s.w, acc[j][3]);
            }
        }

        // ---- DynamicTanh + normalize + Householder reflection ----
        #pragma unroll
        for (int j = 0; j < ROWS_PER_WARP; j++) {
            const int c = (int)((g0 + rowbase + j) & (CC - 1));
            float vv[4];
            float ss = 0.f;
            #pragma unroll
            for (int k = 0; k < 4; k++) {
                const int o = lane + 32 * k;
                float av = As[c * DD + o];
                float cv = Cs[c * DD + o];
                float dv = Ds[c * DD + o];
                float t = tanh_approx(av * acc[j][k]);
                t = fmaf(t, cv, dv);
                vv[k] = t;
                ss = fmaf(t, t, ss);
            }
            #pragma unroll
            for (int off = 16; off; off >>= 1)
                ss += __shfl_xor_sync(0xffffffffu, ss, off);
            const float norm = sqrtf(ss);
            const float inv  = 1.0f / fmaxf(norm, 1e-12f);

            float dot = 0.f;
            #pragma unroll
            for (int k = 0; k < 4; k++) {
                vv[k] *= inv;
                dot = fmaf(vv[k], x[j][k], dot);
            }
            #pragma unroll
            for (int off = 16; off; off >>= 1)
                dot += __shfl_xor_sync(0xffffffffu, dot, off);

            const float m2 = -2.0f * dot;
            #pragma unroll
            for (int k = 0; k < 4; k++)
                x[j][k] = fmaf(m2, vv[k], x[j][k]);
        }
    }

    // ---- write result ----
    #pragma unroll
    for (int j = 0; j < ROWS_PER_WARP; j++) {
        float* orow = out + (g0 + rowbase + j) * DD;
        #pragma unroll
        for (int k = 0; k < 4; k++)
            orow[lane + 32 * k] = x[j][k];
    }
}

extern "C" void kernel_launch(void* const* d_in, const int* in_sizes, int n_in,
                              void* d_out, int out_size)
{
    const float* src = (const float*)d_in[0];   // source [4096,32,128]
    const float* dat = (const float*)d_in[1];   // data   [4096,32,128]
    const float* Wg  = (const float*)d_in[2];   // W      [8,128,128]
    const float* Ag  = (const float*)d_in[3];   // a      [8,32,128]
    const float* Cg  = (const float*)d_in[4];   // c      [8,32,128]
    const float* Dg  = (const float*)d_in[5];   // d      [8,32,128]
    float* out = (float*)d_out;

    cudaFuncSetAttribute(rotation_kernel,
                         cudaFuncAttributeMaxDynamicSharedMemorySize, SMEM_BYTES);

    const int n_rows = BB * CC;                       // 131072
    const int grid = n_rows / ROWS_PER_CTA;           // 2048
    rotation_kernel<<<grid, THREADS, SMEM_BYTES>>>(src, dat, Wg, Ag, Cg, Dg, out);
}

// round 2
// speedup vs baseline: 1.1475x; 1.1475x over previous
#include <cuda_runtime.h>

// Problem constants (fixed by the dataset)
#define BB 4096
#define CC 32
#define DD 128
#define RR 8

#define WARPS 8
#define ROWS_PER_WARP 8
#define ROWS_PER_CTA (WARPS * ROWS_PER_WARP)   // 64
#define THREADS (WARPS * 32)                   // 256

// Shared memory (floats): Ws 128x132 (padded) + Ss 64x128
#define WS_STRIDE 132
#define SMEM_FLOATS (128 * WS_STRIDE + ROWS_PER_CTA * DD)
#define SMEM_BYTES (SMEM_FLOATS * 4)           // 100352 B -> 2 CTAs/SM

__device__ __forceinline__ float tanh_approx(float x) {
    float y;
    asm("tanh.approx.f32 %0, %1;" : "=f"(y) : "f"(x));
    return y;
}

__global__ __launch_bounds__(THREADS, 2)
void rotation_kernel(const float* __restrict__ src,
                     const float* __restrict__ dat,
                     const float* __restrict__ Wg,
                     const float* __restrict__ Ag,
                     const float* __restrict__ Cg,
                     const float* __restrict__ Dg,
                     float* __restrict__ out)
{
    extern __shared__ float sm[];
    float* Ws = sm;                          // [128][132]
    float* Ss = Ws + 128 * WS_STRIDE;        // [64][128]

    const int tid  = threadIdx.x;
    const int lane = tid & 31;
    const int wrp  = tid >> 5;
    const long g0  = (long)blockIdx.x * ROWS_PER_CTA;   // first global row
    const int rowbase = wrp * ROWS_PER_WARP;            // first CTA-local row of this warp

    // ---- stage source tile once (float4 coalesced) ----
    {
        const float4* sg = (const float4*)(src + g0 * DD);
        float4* ss = (float4*)Ss;
        #pragma unroll
        for (int t = 0; t < (ROWS_PER_CTA * DD / 4) / THREADS; t++)   // 8 iters
            ss[tid + t * THREADS] = sg[tid + t * THREADS];
    }

    // ---- x (data) lives in registers across all reflections ----
    float x[ROWS_PER_WARP][4];
    #pragma unroll
    for (int j = 0; j < ROWS_PER_WARP; j++) {
        const float* dr = dat + (g0 + rowbase + j) * DD;
        #pragma unroll
        for (int k = 0; k < 4; k++)
            x[j][k] = __ldg(dr + lane + 32 * k);
    }

    for (int r = 0; r < RR; r++) {
        __syncthreads();   // previous GEMM done with Ws (and Ss staged, r=0)

        // ---- stage W[r] with padded stride (conflict-free compute reads) ----
        {
            const float4* wg = (const float4*)(Wg + (long)r * DD * DD);
            #pragma unroll
            for (int t = 0; t < 16; t++) {
                int idx = tid + t * THREADS;         // 0..4095
                int o   = idx >> 5;                  // output row
                int i4  = idx & 31;                  // float4 index along i
                float4 v4 = wg[idx];
                *(float4*)(Ws + o * WS_STRIDE + i4 * 4) = v4;
            }
        }
        __syncthreads();

        // ---- GEMM: acc[j][k] = sum_i W[r][o][i] * s[row_j][i],  o = lane + 32k ----
        float acc[ROWS_PER_WARP][4];
        #pragma unroll
        for (int j = 0; j < ROWS_PER_WARP; j++)
            #pragma unroll
            for (int k = 0; k < 4; k++) acc[j][k] = 0.f;

        const float* w0p = Ws + (lane +  0) * WS_STRIDE;
        const float* w1p = Ws + (lane + 32) * WS_STRIDE;
        const float* w2p = Ws + (lane + 64) * WS_STRIDE;
        const float* w3p = Ws + (lane + 96) * WS_STRIDE;
        const float* sp  = Ss + rowbase * DD;

        #pragma unroll 2
        for (int i4 = 0; i4 < 32; i4++) {
            float4 w0 = *(const float4*)(w0p + i4 * 4);
            float4 w1 = *(const float4*)(w1p + i4 * 4);
            float4 w2 = *(const float4*)(w2p + i4 * 4);
            float4 w3 = *(const float4*)(w3p + i4 * 4);
            #pragma unroll
            for (int j = 0; j < ROWS_PER_WARP; j++) {
                float4 s = *(const float4*)(sp + j * DD + i4 * 4);
                acc[j][0] = fmaf(w0.x, s.x, acc[j][0]);
                acc[j][0] = fmaf(w0.y, s.y, acc[j][0]);
                acc[j][0] = fmaf(w0.z, s.z, acc[j][0]);
                acc[j][0] = fmaf(w0.w, s.w, acc[j][0]);
                acc[j][1] = fmaf(w1.x, s.x, acc[j][1]);
                acc[j][1] = fmaf(w1.y, s.y, acc[j][1]);
                acc[j][1] = fmaf(w1.z, s.z, acc[j][1]);
                acc[j][1] = fmaf(w1.w, s.w, acc[j][1]);
                acc[j][2] = fmaf(w2.x, s.x, acc[j][2]);
                acc[j][2] = fmaf(w2.y, s.y, acc[j][2]);
                acc[j][2] = fmaf(w2.z, s.z, acc[j][2]);
                acc[j][2] = fmaf(w2.w, s.w, acc[j][2]);
                acc[j][3] = fmaf(w3.x, s.x, acc[j][3]);
                acc[j][3] = fmaf(w3.y, s.y, acc[j][3]);
                acc[j][3] = fmaf(w3.z, s.z, acc[j][3]);
                acc[j][3] = fmaf(w3.w, s.w, acc[j][3]);
            }
        }

        // ---- DynamicTanh + fused (||v||^2, v.x) reduction + Householder ----
        float ssum[ROWS_PER_WARP], dsum[ROWS_PER_WARP];

        #pragma unroll
        for (int j = 0; j < ROWS_PER_WARP; j++) {
            const int c = (rowbase + j) & (CC - 1);
            const long base = ((long)r * CC + c) * DD + lane;
            const float* ap = Ag + base;
            const float* cp = Cg + base;
            const float* dp = Dg + base;
            float sacc = 0.f, dacc = 0.f;
            #pragma unroll
            for (int k = 0; k < 4; k++) {
                float av = __ldg(ap + 32 * k);
                float cv = __ldg(cp + 32 * k);
                float dv = __ldg(dp + 32 * k);
                float t  = tanh_approx(av * acc[j][k]);
                float vv = fmaf(t, cv, dv);
                acc[j][k] = vv;                       // reuse acc as v (unnormalized)
                sacc = fmaf(vv, vv, sacc);
                dacc = fmaf(vv, x[j][k], dacc);
            }
            ssum[j] = sacc;
            dsum[j] = dacc;
        }

        // 16 independent butterfly chains -> SHFL latency hidden by ILP
        #pragma unroll
        for (int off = 16; off; off >>= 1) {
            #pragma unroll
            for (int j = 0; j < ROWS_PER_WARP; j++) {
                ssum[j] += __shfl_xor_sync(0xffffffffu, ssum[j], off);
                dsum[j] += __shfl_xor_sync(0xffffffffu, dsum[j], off);
            }
        }

        // x' = x - 2 * (v.x / max(||v||^2, eps^2)) * v   (normalization folded in)
        #pragma unroll
        for (int j = 0; j < ROWS_PER_WARP; j++) {
            const float m2 = -2.0f * dsum[j] / fmaxf(ssum[j], 1e-24f);
            #pragma unroll
            for (int k = 0; k < 4; k++)
                x[j][k] = fmaf(m2, acc[j][k], x[j][k]);
        }
    }

    // ---- write result ----
    #pragma unroll
    for (int j = 0; j < ROWS_PER_WARP; j++) {
        float* orow = out + (g0 + rowbase + j) * DD;
        #pragma unroll
        for (int k = 0; k < 4; k++)
            orow[lane + 32 * k] = x[j][k];
    }
}

extern "C" void kernel_launch(void* const* d_in, const int* in_sizes, int n_in,
                              void* d_out, int out_size)
{
    const float* src = (const float*)d_in[0];   // source [4096,32,128]
    const float* dat = (const float*)d_in[1];   // data   [4096,32,128]
    const float* Wg  = (const float*)d_in[2];   // W      [8,128,128]
    const float* Ag  = (const float*)d_in[3];   // a      [8,32,128]
    const float* Cg  = (const float*)d_in[4];   // c      [8,32,128]
    const float* Dg  = (const float*)d_in[5];   // d      [8,32,128]
    float* out = (float*)d_out;

    cudaFuncSetAttribute(rotation_kernel,
                         cudaFuncAttributeMaxDynamicSharedMemorySize, SMEM_BYTES);

    const int n_rows = BB * CC;                       // 131072
    const int grid = n_rows / ROWS_PER_CTA;           // 2048
    rotation_kernel<<<grid, THREADS, SMEM_BYTES>>>(src, dat, Wg, Ag, Cg, Dg, out);
}

// round 4
// speedup vs baseline: 2.6023x; 2.2677x over previous
#include <cuda_runtime.h>
#include <cuda_bf16.h>
#include <cstdint>

// Problem constants
#define BB 4096
#define CC 32
#define DD 128
#define RR 8
#define ROWS 128             // M rows per CTA
#define THREADS 512          // 16 warps: (mw 0..7) x (nh 0..1)

#define BSTR 136             // bf16 row stride (272B) for S/W tiles: ldmatrix conflict-free
#define ASTR 132             // float row stride for a/c/d tiles (<=2-way LDS conflicts)

// ---- smem layout (byte offsets) ----
#define OFF_SHI 0
#define OFF_SLO (OFF_SHI + 128 * BSTR * 2)
#define OFF_WHI (OFF_SLO + 128 * BSTR * 2)
#define OFF_WLO (OFF_WHI + 128 * BSTR * 2)
#define OFF_A   (OFF_WLO + 128 * BSTR * 2)
#define OFF_C   (OFF_A + CC * ASTR * 4)
#define OFF_Dd  (OFF_C + CC * ASTR * 4)
#define OFF_RS  (OFF_Dd + CC * ASTR * 4)
#define OFF_RD  (OFF_RS + 128 * 2 * 4)
#define SMEM_BYTES (OFF_RD + 128 * 2 * 4)   // ~187.5 KB

__device__ __forceinline__ uint32_t smem_u32(const void* p) {
    uint32_t a;
    asm("{ .reg .u64 t; cvta.to.shared.u64 t, %1; cvt.u32.u64 %0, t; }" : "=r"(a) : "l"(p));
    return a;
}
__device__ __forceinline__ float tanh_approx(float x) {
    float y;
    asm("tanh.approx.f32 %0, %1;" : "=f"(y) : "f"(x));
    return y;
}
__device__ __forceinline__ uint32_t pack_bf2(float x, float y) {
    __nv_bfloat162 h = __floats2bfloat162_rn(x, y);
    return *reinterpret_cast<uint32_t*>(&h);
}
__device__ __forceinline__ float bf_res(float x) {
    __nv_bfloat16 h = __float2bfloat16_rn(x);
    return x - __bfloat162float(h);
}

#define LDSM4(r, addr) \
    asm volatile("ldmatrix.sync.aligned.m8n8.x4.shared.b16 {%0,%1,%2,%3}, [%4];" \
        : "=r"((r)[0]), "=r"((r)[1]), "=r"((r)[2]), "=r"((r)[3]) : "r"(addr))

#define MMA_BF16(c, a, b0, b1) \
    asm volatile("mma.sync.aligned.m16n8k16.row.col.f32.bf16.bf16.f32 " \
        "{%0,%1,%2,%3},{%4,%5,%6,%7},{%8,%9},{%0,%1,%2,%3};" \
        : "+f"((c)[0]), "+f"((c)[1]), "+f"((c)[2]), "+f"((c)[3]) \
        : "r"((a)[0]), "r"((a)[1]), "r"((a)[2]), "r"((a)[3]), "r"(b0), "r"(b1))

__global__ __launch_bounds__(THREADS, 1)
void rotation_mma_kernel(const float* __restrict__ src,
                         const float* __restrict__ dat,
                         const float* __restrict__ Wg,
                         const float* __restrict__ Ag,
                         const float* __restrict__ Cg,
                         const float* __restrict__ Dg,
                         float* __restrict__ out)
{
    extern __shared__ char smem[];
    const uint32_t sb = smem_u32(smem);
    const int tid  = threadIdx.x;
    const int lane = tid & 31;
    const int warp = tid >> 5;
    const int mw   = warp >> 1;          // M16 strip (0..7)
    const int nh   = warp & 1;           // N64 half (0..1)
    const long g0  = (long)blockIdx.x * ROWS;

    // ---- stage S hi/lo bf16 once: [row][k], stride BSTR ----
    {
        const float4* sg = (const float4*)(src + g0 * DD);
        #pragma unroll
        for (int t = 0; t < 8; t++) {
            int idx4 = tid + t * THREADS;          // 0..4095
            int row  = idx4 >> 5;
            int k4   = idx4 & 31;
            float4 f = __ldg(sg + idx4);
            uint2 hi, lo;
            hi.x = pack_bf2(f.x, f.y);  hi.y = pack_bf2(f.z, f.w);
            lo.x = pack_bf2(bf_res(f.x), bf_res(f.y));
            lo.y = pack_bf2(bf_res(f.z), bf_res(f.w));
            int boff = (row * BSTR + k4 * 4) * 2;
            *(uint2*)(smem + OFF_SHI + boff) = hi;
            *(uint2*)(smem + OFF_SLO + boff) = lo;
        }
    }

    // ---- x resident in fragment layout: x[nt][j], j = rs*2 + s ----
    // row = mw*16 + (lane>>2) + 8*rs ; col = nh*64 + nt*8 + 2*(lane&3) + s
    const int q    = lane >> 2;
    const int colb = nh * 64 + 2 * (lane & 3);
    const int row0 = mw * 16 + q;        // rs=0 row
    float x[8][4];
    {
        const float* d0p = dat + (g0 + row0) * DD + colb;
        const float* d1p = dat + (g0 + row0 + 8) * DD + colb;
        #pragma unroll
        for (int nt = 0; nt < 8; nt++) {
            float2 f0 = *(const float2*)(d0p + nt * 8);
            float2 f1 = *(const float2*)(d1p + nt * 8);
            x[nt][0] = f0.x; x[nt][1] = f0.y;
            x[nt][2] = f1.x; x[nt][3] = f1.y;
        }
    }

    float* RS = (float*)(smem + OFF_RS);
    float* RD = (float*)(smem + OFF_RD);

    // ldmatrix source addresses (warp-invariant parts precomputed)
    const uint32_t a_row = (uint32_t)(mw * 16 + (lane & 15));
    const uint32_t a_k0  = (uint32_t)((lane >> 4) * 8);
    const uint32_t b_n   = (uint32_t)(nh * 64 + (lane & 7) + ((lane >> 4) << 3));
    const uint32_t b_k0  = (uint32_t)(((lane >> 3) & 1) * 8);

    for (int r = 0; r < RR; r++) {
        __syncthreads();   // everyone done with previous W/acd/RS

        // ---- stage W[r] hi/lo bf16: [o][k] stride BSTR ----
        {
            const float4* wg = (const float4*)(Wg + (size_t)r * DD * DD);
            #pragma unroll
            for (int t = 0; t < 8; t++) {
                int idx4 = tid + t * THREADS;
                int o  = idx4 >> 5;
                int k4 = idx4 & 31;
                float4 f = __ldg(wg + idx4);
                uint2 hi, lo;
                hi.x = pack_bf2(f.x, f.y);  hi.y = pack_bf2(f.z, f.w);
                lo.x = pack_bf2(bf_res(f.x), bf_res(f.y));
                lo.y = pack_bf2(bf_res(f.z), bf_res(f.w));
                int boff = (o * BSTR + k4 * 4) * 2;
                *(uint2*)(smem + OFF_WHI + boff) = hi;
                *(uint2*)(smem + OFF_WLO + boff) = lo;
            }
        }
        // ---- stage a/c/d[r]: [ch][col] stride ASTR ----
        {
            const float4* ag = (const float4*)(Ag + (size_t)r * CC * DD);
            const float4* cg = (const float4*)(Cg + (size_t)r * CC * DD);
            const float4* dg = (const float4*)(Dg + (size_t)r * CC * DD);
            float* As = (float*)(smem + OFF_A);
            float* Cs = (float*)(smem + OFF_C);
            float* Ds = (float*)(smem + OFF_Dd);
            #pragma unroll
            for (int t = 0; t < 2; t++) {
                int idx4 = tid + t * THREADS;       // 0..1023
                int ch = idx4 >> 5;
                int c4 = (idx4 & 31) * 4;
                float4 fa = __ldg(ag + idx4);
                float4 fc = __ldg(cg + idx4);
                float4 fd = __ldg(dg + idx4);
                *(float4*)(As + ch * ASTR + c4) = fa;
                *(float4*)(Cs + ch * ASTR + c4) = fc;
                *(float4*)(Ds + ch * ASTR + c4) = fd;
            }
        }
        __syncthreads();

        // ---- tensor GEMM: acc[nt] = v_raw tile (M16 x N64 per warp) ----
        float acc[8][4];
        #pragma unroll
        for (int nt = 0; nt < 8; nt++)
            #pragma unroll
            for (int j = 0; j < 4; j++) acc[nt][j] = 0.f;

        #pragma unroll
        for (int kt = 0; kt < 8; kt++) {
            uint32_t ahi[4], alo[4];
            uint32_t aoff = (a_row * BSTR + (uint32_t)kt * 16 + a_k0) * 2;
            LDSM4(ahi, sb + OFF_SHI + aoff);
            LDSM4(alo, sb + OFF_SLO + aoff);
            #pragma unroll
            for (int nt2 = 0; nt2 < 4; nt2++) {
                uint32_t bhi[4], blo[4];
                uint32_t boff = ((b_n + (uint32_t)nt2 * 16) * BSTR + (uint32_t)kt * 16 + b_k0) * 2;
                LDSM4(bhi, sb + OFF_WHI + boff);
                LDSM4(blo, sb + OFF_WLO + boff);
                MMA_BF16(acc[2 * nt2],     ahi, bhi[0], bhi[1]);
                MMA_BF16(acc[2 * nt2],     alo, bhi[0], bhi[1]);
                MMA_BF16(acc[2 * nt2],     ahi, blo[0], blo[1]);
                MMA_BF16(acc[2 * nt2 + 1], ahi, bhi[2], bhi[3]);
                MMA_BF16(acc[2 * nt2 + 1], alo, bhi[2], bhi[3]);
                MMA_BF16(acc[2 * nt2 + 1], ahi, blo[2], blo[3]);
            }
        }

        // ---- epilogue: tanh/a/c/d + fused (||v||^2, v.x) + reflect ----
        const float* As = (const float*)(smem + OFF_A);
        const float* Cs = (const float*)(smem + OFF_C);
        const float* Ds = (const float*)(smem + OFF_Dd);
        const int ch0 = row0 & 31;          // (mw&1)*16 + q, <= 23
        const int ch1 = ch0 + 8;

        float s0 = 0.f, s1 = 0.f, d0 = 0.f, d1 = 0.f;
        #pragma unroll
        for (int nt = 0; nt < 8; nt++) {
            const int col = colb + nt * 8;
            const int o00 = ch0 * ASTR + col;
            const int o10 = ch1 * ASTR + col;
            float v;
            v = fmaf(tanh_approx(As[o00] * acc[nt][0]), Cs[o00], Ds[o00]);
            acc[nt][0] = v; s0 = fmaf(v, v, s0); d0 = fmaf(v, x[nt][0], d0);
            v = fmaf(tanh_approx(As[o00 + 1] * acc[nt][1]), Cs[o00 + 1], Ds[o00 + 1]);
            acc[nt][1] = v; s0 = fmaf(v, v, s0); d0 = fmaf(v, x[nt][1], d0);
            v = fmaf(tanh_approx(As[o10] * acc[nt][2]), Cs[o10], Ds[o10]);
            acc[nt][2] = v; s1 = fmaf(v, v, s1); d1 = fmaf(v, x[nt][2], d1);
            v = fmaf(tanh_approx(As[o10 + 1] * acc[nt][3]), Cs[o10 + 1], Ds[o10 + 1]);
            acc[nt][3] = v; s1 = fmaf(v, v, s1); d1 = fmaf(v, x[nt][3], d1);
        }
        // reduce within quad (lanes sharing rows)
        #pragma unroll
        for (int off = 1; off <= 2; off <<= 1) {
            s0 += __shfl_xor_sync(0xffffffffu, s0, off);
            s1 += __shfl_xor_sync(0xffffffffu, s1, off);
            d0 += __shfl_xor_sync(0xffffffffu, d0, off);
            d1 += __shfl_xor_sync(0xffffffffu, d1, off);
        }
        if ((lane & 3) == 0) {
            RS[row0 * 2 + nh] = s0;  RS[(row0 + 8) * 2 + nh] = s1;
            RD[row0 * 2 + nh] = d0;  RD[(row0 + 8) * 2 + nh] = d1;
        }
        __syncthreads();
        const float st0 = RS[row0 * 2] + RS[row0 * 2 + 1];
        const float dt0 = RD[row0 * 2] + RD[row0 * 2 + 1];
        const float st1 = RS[(row0 + 8) * 2] + RS[(row0 + 8) * 2 + 1];
        const float dt1 = RD[(row0 + 8) * 2] + RD[(row0 + 8) * 2 + 1];
        const float m20 = -2.0f * dt0 / fmaxf(st0, 1e-24f);
        const float m21 = -2.0f * dt1 / fmaxf(st1, 1e-24f);
        #pragma unroll
        for (int nt = 0; nt < 8; nt++) {
            x[nt][0] = fmaf(m20, acc[nt][0], x[nt][0]);
            x[nt][1] = fmaf(m20, acc[nt][1], x[nt][1]);
            x[nt][2] = fmaf(m21, acc[nt][2], x[nt][2]);
            x[nt][3] = fmaf(m21, acc[nt][3], x[nt][3]);
        }
    }

    // ---- write result ----
    {
        float* o0p = out + (g0 + row0) * DD + colb;
        float* o1p = out + (g0 + row0 + 8) * DD + colb;
        #pragma unroll
        for (int nt = 0; nt < 8; nt++) {
            float2 f0, f1;
            f0.x = x[nt][0]; f0.y = x[nt][1];
            f1.x = x[nt][2]; f1.y = x[nt][3];
            *(float2*)(o0p + nt * 8) = f0;
            *(float2*)(o1p + nt * 8) = f1;
        }
    }
}

extern "C" void kernel_launch(void* const* d_in, const int* in_sizes, int n_in,
                              void* d_out, int out_size)
{
    const float* src = (const float*)d_in[0];   // source [4096,32,128]
    const float* dat = (const float*)d_in[1];   // data   [4096,32,128]
    const float* Wg  = (const float*)d_in[2];   // W      [8,128,128]
    const float* Ag  = (const float*)d_in[3];   // a      [8,32,128]
    const float* Cg  = (const float*)d_in[4];   // c      [8,32,128]
    const float* Dg  = (const float*)d_in[5];   // d      [8,32,128]
    float* out = (float*)d_out;

    cudaFuncSetAttribute(rotation_mma_kernel,
                         cudaFuncAttributeMaxDynamicSharedMemorySize, SMEM_BYTES);

    const int grid = (BB * CC) / ROWS;          // 1024
    rotation_mma_kernel<<<grid, THREADS, SMEM_BYTES>>>(src, dat, Wg, Ag, Cg, Dg, out);
}